// round 5
// baseline (speedup 1.0000x reference)
#include <cuda_runtime.h>
#include <cuda_bf16.h>
#include <cstdint>
#include <cstddef>

// ============================================================================
// proj[b,c] = sum_{i,j} t[b,i] * W[c, i*512+j] * f[b,j]   (B=2048, F=512, C=64)
// out = relu(relu(proj + bp) @ W1^T + b1) @ W2^T + b2
//
// tcgen05 is unavailable (harness PTX target is sm_103, no 'a' features), so:
//   tf32 mma.sync.m16n8k8 warp GEMM, single pass (rel_err ~3e-4).
//   convT / convW pre-convert fp32 -> tf32 bits in EXACT mma fragment order,
//   so the GEMM smem reads are conflict-free lds.128 / lds.64.
//   GEMM: per (btile 256, jt 128, c): P = T @ M_c slice, K=512, cp.async x4 stages.
//   Epilogue: partial[b,c] += sum_j P[b,j]*f[b,j]  (8 deterministic slices).
//   MLP kernel: sum slices, bias, relu, 64->32->1.
// ============================================================================

// Fragment-ordered operands (tf32 bit patterns):
// g_T  [btile(8)][kc(64)][mt(16)][lane(32)][4]   : A frags  (4 MB)
// g_W  [c(64)][jt(4)][kc(64)][nt(16)][lane(32)][2]: B frags (67 MB)
__device__ uint32_t g_T[8 * 64 * 16 * 32 * 4];            // 1,048,576
__device__ uint32_t g_W[64 * 4 * 64 * 16 * 32 * 2];       // 16,777,216
__device__ float    g_partial[8 * 2048 * 64];             // 4 MB

// ---------------- helpers ----------------
__device__ __forceinline__ uint32_t f2tf32(float x) {
    uint32_t r;
    asm("cvt.rna.tf32.f32 %0, %1;" : "=r"(r) : "f"(x));
    return r;
}
__device__ __forceinline__ void cp16(uint32_t dst_smem, const void* src) {
    asm volatile("cp.async.cg.shared.global [%0], [%1], 16;" :: "r"(dst_smem), "l"(src));
}
__device__ __forceinline__ void cp_commit() {
    asm volatile("cp.async.commit_group;" ::: "memory");
}
__device__ __forceinline__ void cp_wait2() {
    asm volatile("cp.async.wait_group 2;" ::: "memory");
}
__device__ __forceinline__ void mma_tf32(float* d, const uint32_t* a, const uint32_t* b) {
    asm volatile(
        "mma.sync.aligned.m16n8k8.row.col.f32.tf32.tf32.f32 "
        "{%0,%1,%2,%3},{%4,%5,%6,%7},{%8,%9},{%0,%1,%2,%3};"
        : "+f"(d[0]), "+f"(d[1]), "+f"(d[2]), "+f"(d[3])
        : "r"(a[0]), "r"(a[1]), "r"(a[2]), "r"(a[3]), "r"(b[0]), "r"(b[1]));
}

// ---------------- convT: t -> A fragments ----------------
// A 16x8 tile fragment for thread t: a0=(r,c)=(t/4, t%4), a1=(t/4+8, t%4),
// a2=(t/4, t%4+4), a3=(t/4+8, t%4+4).
__global__ void convT_kernel(const float* __restrict__ t) {
    int gid = blockIdx.x * 256 + threadIdx.x;     // 262144 threads
    int lane  = gid & 31;
    int mt    = (gid >> 5) & 15;
    int kc    = (gid >> 9) & 63;
    int btile = gid >> 15;
    int row0 = btile * 256 + mt * 16 + (lane >> 2);
    int col0 = kc * 8 + (lane & 3);
    uint32_t v[4];
#pragma unroll
    for (int r = 0; r < 4; r++) {
        int row = row0 + 8 * (r & 1);
        int col = col0 + 4 * (r >> 1);
        v[r] = f2tf32(t[(size_t)row * 512 + col]);
    }
    *(uint4*)&g_T[(size_t)gid * 4] = make_uint4(v[0], v[1], v[2], v[3]);
}

// ---------------- convW: W -> B fragments (transposed) ----------------
// B 8x8 (k x n) tile fragment for thread t: b0=(k,n)=(t%4, t/4), b1=(t%4+4, t/4).
// Bt[n][k] = W[c, k*512 + n]  (n = global j, k = global i).
__global__ void convW_kernel(const float* __restrict__ W) {
    int gid = blockIdx.x * 256 + threadIdx.x;     // 8,388,608 threads
    int lane = gid & 31;
    int nt   = (gid >> 5) & 15;
    int kc   = (gid >> 9) & 63;
    int jt   = (gid >> 15) & 3;
    int c    = gid >> 17;
    int n  = jt * 128 + nt * 8 + (lane >> 2);
    int k0 = kc * 8 + (lane & 3);
    const float* base = W + (size_t)c * 262144 + n;
    uint32_t v0 = f2tf32(base[(size_t)k0 * 512]);
    uint32_t v1 = f2tf32(base[(size_t)(k0 + 4) * 512]);
    *(uint2*)&g_W[(size_t)gid * 2] = make_uint2(v0, v1);
}

// ---------------- GEMM + f-dot epilogue ----------------
// CTA tile 256(m=b) x 128(n=j), K=512. 8 warps: mw = warp%4 (64 rows), nw = warp/4 (64 cols).
// smem: 4 stages x 12288 B (A 8KB frag-order + B 4KB frag-order) = 49152 B static.
__global__ __launch_bounds__(256, 1) void gemm_kernel(const float* __restrict__ f_feat) {
    __shared__ uint32_t smem[12288];   // 48 KB
    int tid = threadIdx.x;
    int lane = tid & 31, warp = tid >> 5;
    int mw = warp & 3, nw = warp >> 2;
    int btile = blockIdx.x, jt = blockIdx.y, c = blockIdx.z;

    const char* gA = (const char*)g_T + (size_t)btile * 64 * 8192;
    const char* gB = (const char*)g_W + (size_t)((c * 4 + jt) * 64) * 4096;
    uint32_t sbase = (uint32_t)__cvta_generic_to_shared(smem);

    // prime 3 stages
#pragma unroll
    for (int s = 0; s < 3; s++) {
        uint32_t d = sbase + s * 12288;
        cp16(d + tid * 16,          gA + (size_t)s * 8192 + tid * 16);
        cp16(d + 4096 + tid * 16,   gA + (size_t)s * 8192 + 4096 + tid * 16);
        cp16(d + 8192 + tid * 16,   gB + (size_t)s * 4096 + tid * 16);
        cp_commit();
    }

    float acc[4][8][4];
#pragma unroll
    for (int mt = 0; mt < 4; mt++)
#pragma unroll
        for (int nt = 0; nt < 8; nt++)
#pragma unroll
            for (int q = 0; q < 4; q++) acc[mt][nt][q] = 0.f;

    for (int kc = 0; kc < 64; kc++) {
        cp_wait2();
        __syncthreads();
        int s = kc & 3;
        const uint32_t* sA = smem + s * 3072;
        const uint32_t* sB = smem + s * 3072 + 2048;

        uint32_t bfr[8][2];
#pragma unroll
        for (int nt = 0; nt < 8; nt++) {
            uint2 bb = *(const uint2*)&sB[((nw * 8 + nt) * 32 + lane) * 2];
            bfr[nt][0] = bb.x; bfr[nt][1] = bb.y;
        }
#pragma unroll
        for (int mt = 0; mt < 4; mt++) {
            uint4 aa = *(const uint4*)&sA[((mw * 4 + mt) * 32 + lane) * 4];
            uint32_t afr[4] = {aa.x, aa.y, aa.z, aa.w};
#pragma unroll
            for (int nt = 0; nt < 8; nt++)
                mma_tf32(acc[mt][nt], afr, bfr[nt]);
        }

        if (kc < 61) {
            int kn = kc + 3;
            uint32_t d = sbase + (kn & 3) * 12288;
            cp16(d + tid * 16,        gA + (size_t)kn * 8192 + tid * 16);
            cp16(d + 4096 + tid * 16, gA + (size_t)kn * 8192 + 4096 + tid * 16);
            cp16(d + 8192 + tid * 16, gB + (size_t)kn * 4096 + tid * 16);
        }
        cp_commit();   // empty group when kc >= 61 keeps wait arithmetic uniform
    }

    // ---------------- epilogue: partial[b,c] = sum_j P[b,j] * f[b,j] ----------------
    float* fs = (float*)smem;   // 64 rows x 132 floats (padded) = 33792 B
    for (int p = 0; p < 4; p++) {
        __syncthreads();
        // stage f rows [btile*256 + p*64, +64), cols [jt*128, +128)
        for (int i = tid; i < 64 * 32; i += 256) {
            int row = i >> 5, cg = i & 31;
            float4 v = *(const float4*)&f_feat[(size_t)(btile * 256 + p * 64 + row) * 512 + jt * 128 + cg * 4];
            *(float4*)&fs[row * 132 + cg * 4] = v;
        }
        __syncthreads();
        if (mw == p) {
#pragma unroll
            for (int mt = 0; mt < 4; mt++) {
#pragma unroll
                for (int h = 0; h < 2; h++) {
                    int fl = mt * 16 + (lane >> 2) + 8 * h;   // local row 0..63
                    float sum = 0.f;
#pragma unroll
                    for (int nt = 0; nt < 8; nt++) {
                        float2 fv = *(const float2*)&fs[fl * 132 + nw * 64 + nt * 8 + 2 * (lane & 3)];
                        sum = fmaf(acc[mt][nt][h * 2], fv.x, sum);
                        sum = fmaf(acc[mt][nt][h * 2 + 1], fv.y, sum);
                    }
                    sum += __shfl_xor_sync(0xffffffffu, sum, 1);
                    sum += __shfl_xor_sync(0xffffffffu, sum, 2);
                    if ((lane & 3) == 0) {
                        int b = btile * 256 + p * 64 + fl;
                        g_partial[(size_t)(jt * 2 + nw) * 131072 + (size_t)b * 64 + c] = sum;
                    }
                }
            }
        }
    }
}

// ---------------- MLP: sum 8 slices + bias + relu + 64->32->1 ----------------
__global__ void mlp_kernel(const float* __restrict__ b_proj, const float* __restrict__ W1,
                           const float* __restrict__ b1, const float* __restrict__ W2,
                           const float* __restrict__ b2, float* __restrict__ out) {
    __shared__ float sW1[2048], sb1[32], sW2[32], sbp[64];
    int tid = threadIdx.x;
    for (int i = tid; i < 2048; i += 256) sW1[i] = W1[i];
    if (tid < 32) { sb1[tid] = b1[tid]; sW2[tid] = W2[tid]; }
    if (tid < 64) sbp[tid] = b_proj[tid];
    __syncthreads();

    int b = blockIdx.x * 256 + tid;
    float h[64];
#pragma unroll
    for (int cc = 0; cc < 64; cc++) {
        float v = sbp[cc];
#pragma unroll
        for (int s = 0; s < 8; s++)
            v += g_partial[(size_t)s * 131072 + (size_t)b * 64 + cc];
        h[cc] = fmaxf(v, 0.f);
    }
    float logit = b2[0];
#pragma unroll
    for (int k = 0; k < 32; k++) {
        float a = sb1[k];
#pragma unroll
        for (int cc = 0; cc < 64; cc++)
            a = fmaf(h[cc], sW1[k * 64 + cc], a);
        logit = fmaf(fmaxf(a, 0.f), sW2[k], logit);
    }
    out[b] = logit;
}

// ---------------- launcher ----------------
extern "C" void kernel_launch(void* const* d_in, const int* in_sizes, int n_in,
                              void* d_out, int out_size) {
    const float* t_feat = (const float*)d_in[0];
    const float* f_feat = (const float*)d_in[1];
    const float* W_proj = (const float*)d_in[2];
    const float* b_proj = (const float*)d_in[3];
    const float* W1     = (const float*)d_in[4];
    const float* b1     = (const float*)d_in[5];
    const float* W2     = (const float*)d_in[6];
    const float* b2     = (const float*)d_in[7];
    float* out = (float*)d_out;

    convT_kernel<<<1024, 256>>>(t_feat);
    convW_kernel<<<32768, 256>>>(W_proj);
    dim3 grid(8, 4, 64);   // (btile, jt, c) — btile fastest keeps W slice hot in L2
    gemm_kernel<<<grid, 256>>>(f_feat);
    mlp_kernel<<<8, 256>>>(b_proj, W1, b1, W2, b2, out);
}

// round 6
// speedup vs baseline: 1.1232x; 1.1232x over previous
#include <cuda_runtime.h>
#include <cuda_bf16.h>
#include <cstdint>
#include <cstddef>

// ============================================================================
// proj[b,c] = sum_{i,j} t[b,i] * W[c, i*512+j] * f[b,j]   (B=2048, F=512, C=64)
// out = relu(relu(proj + bp) @ W1^T + b1) @ W2^T + b2
//
// tf32 mma.sync.m16n8k8 warp GEMM (tcgen05 unavailable at harness's sm_103 target).
//   conv:  t,W -> tf32 bits in EXACT mma fragment order (conflict-free smem reads)
//   gemm:  per (btile 256, jt 128, c): P = T @ M_c slice, K=512.
//          K-chunk 16, 4-stage cp.async pipeline (96KB dynamic smem).
//          Epilogue: partial[b,c] = sum_j P[b,j]*f[b,j] (8 deterministic slices).
//   mlp:   sum slices, bias, relu, 64->32->1.  (64 blocks x 32 thr)
// ============================================================================

// g_T  [btile(8)][kc8(64)][mt(16)][lane(32)][4]    (4 MB)
// g_W  [c(64)][jt(4)][kc8(64)][nt(16)][lane(32)][2] (64 MB)
__device__ uint32_t g_T[8 * 64 * 16 * 32 * 4];
__device__ uint32_t g_W[64 * 4 * 64 * 16 * 32 * 2];
__device__ float    g_partial[8 * 2048 * 64];

// ---------------- helpers ----------------
__device__ __forceinline__ uint32_t f2tf32(float x) {
    uint32_t r;
    asm("cvt.rna.tf32.f32 %0, %1;" : "=r"(r) : "f"(x));
    return r;
}
__device__ __forceinline__ void cp16(uint32_t dst_smem, const void* src) {
    asm volatile("cp.async.cg.shared.global [%0], [%1], 16;" :: "r"(dst_smem), "l"(src));
}
__device__ __forceinline__ void cp_commit() {
    asm volatile("cp.async.commit_group;" ::: "memory");
}
__device__ __forceinline__ void cp_wait2() {
    asm volatile("cp.async.wait_group 2;" ::: "memory");
}
__device__ __forceinline__ void mma_tf32(float* d, const uint32_t* a, const uint32_t* b) {
    asm volatile(
        "mma.sync.aligned.m16n8k8.row.col.f32.tf32.tf32.f32 "
        "{%0,%1,%2,%3},{%4,%5,%6,%7},{%8,%9},{%0,%1,%2,%3};"
        : "+f"(d[0]), "+f"(d[1]), "+f"(d[2]), "+f"(d[3])
        : "r"(a[0]), "r"(a[1]), "r"(a[2]), "r"(a[3]), "r"(b[0]), "r"(b[1]));
}

// ---------------- conv (merged): t and W -> fragment-ordered tf32 ----------------
// blocks [0,1024): convT.  A 16x8 frag, thread t: a0=(t/4,t%4) a1=(+8,.) a2=(.,+4) a3=(+8,+4)
// blocks [1024,33792): convW. B 8x8 (k x n) frag: b0=(t%4, t/4), b1=(t%4+4, t/4)
__global__ void conv_kernel(const float* __restrict__ t, const float* __restrict__ W) {
    if (blockIdx.x < 1024) {
        int gid = blockIdx.x * 256 + threadIdx.x;
        int lane  = gid & 31;
        int mt    = (gid >> 5) & 15;
        int kc    = (gid >> 9) & 63;
        int btile = gid >> 15;
        int row0 = btile * 256 + mt * 16 + (lane >> 2);
        int col0 = kc * 8 + (lane & 3);
        uint32_t v[4];
#pragma unroll
        for (int r = 0; r < 4; r++) {
            int row = row0 + 8 * (r & 1);
            int col = col0 + 4 * (r >> 1);
            v[r] = f2tf32(t[(size_t)row * 512 + col]);
        }
        *(uint4*)&g_T[(size_t)gid * 4] = make_uint4(v[0], v[1], v[2], v[3]);
    } else {
        int gid = (blockIdx.x - 1024) * 256 + threadIdx.x;
        int lane = gid & 31;
        int nt   = (gid >> 5) & 15;
        int kc   = (gid >> 9) & 63;
        int jt   = (gid >> 15) & 3;
        int c    = gid >> 17;
        int n  = jt * 128 + nt * 8 + (lane >> 2);
        int k0 = kc * 8 + (lane & 3);
        const float* base = W + (size_t)c * 262144 + n;
        uint32_t v0 = f2tf32(base[(size_t)k0 * 512]);
        uint32_t v1 = f2tf32(base[(size_t)(k0 + 4) * 512]);
        *(uint2*)&g_W[(size_t)gid * 2] = make_uint2(v0, v1);
    }
}

// ---------------- GEMM + f-dot epilogue ----------------
// CTA tile 256(m) x 128(n), K=512 in 32 chunks of 16. 8 warps: mw=warp%4, nw=warp/4 (64x64).
// Dynamic smem: 4 stages x 24576 B (A 16KB + B 8KB, frag-order, contiguous in gmem).
static constexpr uint32_t STAGE_SZ  = 24576;
static constexpr uint32_t SMEM_GEMM = 4 * STAGE_SZ;  // 98304

__global__ __launch_bounds__(256, 1) void gemm_kernel(const float* __restrict__ f_feat) {
    extern __shared__ __align__(16) unsigned char smem_dyn[];
    uint32_t* smem = (uint32_t*)smem_dyn;
    int tid = threadIdx.x;
    int lane = tid & 31, warp = tid >> 5;
    int mw = warp & 3, nw = warp >> 2;
    int btile = blockIdx.x, jt = blockIdx.y, c = blockIdx.z;

    const char* gA = (const char*)g_T + (size_t)btile * 64 * 8192;           // 64 k8-chunks
    const char* gB = (const char*)g_W + (size_t)((c * 4 + jt) * 64) * 4096;
    uint32_t sbase = (uint32_t)__cvta_generic_to_shared(smem);

    // prime 3 stages (each stage: A 16KB = 64B/thr, B 8KB = 32B/thr)
#pragma unroll
    for (int s = 0; s < 3; s++) {
        uint32_t d = sbase + s * STAGE_SZ;
#pragma unroll
        for (int q = 0; q < 4; q++)
            cp16(d + q * 4096 + tid * 16, gA + (size_t)s * 16384 + q * 4096 + tid * 16);
#pragma unroll
        for (int q = 0; q < 2; q++)
            cp16(d + 16384 + q * 4096 + tid * 16, gB + (size_t)s * 8192 + q * 4096 + tid * 16);
        cp_commit();
    }

    float acc[4][8][4];
#pragma unroll
    for (int mt = 0; mt < 4; mt++)
#pragma unroll
        for (int nt = 0; nt < 8; nt++)
#pragma unroll
            for (int q = 0; q < 4; q++) acc[mt][nt][q] = 0.f;

    for (int it = 0; it < 32; it++) {
        cp_wait2();
        __syncthreads();
        int s = it & 3;
        const uint32_t* sA = smem + s * (STAGE_SZ / 4);
        const uint32_t* sB = sA + 4096;

#pragma unroll
        for (int sub = 0; sub < 2; sub++) {
            const uint32_t* pA = sA + sub * 2048;
            const uint32_t* pB = sB + sub * 1024;
            uint32_t bfr[8][2];
#pragma unroll
            for (int nt = 0; nt < 8; nt++) {
                uint2 bb = *(const uint2*)&pB[((nw * 8 + nt) * 32 + lane) * 2];
                bfr[nt][0] = bb.x; bfr[nt][1] = bb.y;
            }
#pragma unroll
            for (int mt = 0; mt < 4; mt++) {
                uint4 aa = *(const uint4*)&pA[((mw * 4 + mt) * 32 + lane) * 4];
                uint32_t afr[4] = {aa.x, aa.y, aa.z, aa.w};
#pragma unroll
                for (int nt = 0; nt < 8; nt++)
                    mma_tf32(acc[mt][nt], afr, bfr[nt]);
            }
        }

        if (it < 29) {
            int kn = it + 3;
            uint32_t d = sbase + (kn & 3) * STAGE_SZ;
#pragma unroll
            for (int q = 0; q < 4; q++)
                cp16(d + q * 4096 + tid * 16, gA + (size_t)kn * 16384 + q * 4096 + tid * 16);
#pragma unroll
            for (int q = 0; q < 2; q++)
                cp16(d + 16384 + q * 4096 + tid * 16, gB + (size_t)kn * 8192 + q * 4096 + tid * 16);
        }
        cp_commit();   // empty group when it >= 29 keeps wait arithmetic uniform
    }

    // ---------------- epilogue: partial[b,c] = sum_j P[b,j] * f[b,j] ----------------
    float* fs = (float*)smem;   // 64 rows x 132 floats (padded)
    for (int p = 0; p < 4; p++) {
        __syncthreads();
        for (int i = tid; i < 64 * 32; i += 256) {
            int row = i >> 5, cg = i & 31;
            float4 v = *(const float4*)&f_feat[(size_t)(btile * 256 + p * 64 + row) * 512 + jt * 128 + cg * 4];
            *(float4*)&fs[row * 132 + cg * 4] = v;
        }
        __syncthreads();
        if (mw == p) {
#pragma unroll
            for (int mt = 0; mt < 4; mt++) {
#pragma unroll
                for (int h = 0; h < 2; h++) {
                    int fl = mt * 16 + (lane >> 2) + 8 * h;   // local row 0..63
                    float sum = 0.f;
#pragma unroll
                    for (int nt = 0; nt < 8; nt++) {
                        float2 fv = *(const float2*)&fs[fl * 132 + nw * 64 + nt * 8 + 2 * (lane & 3)];
                        sum = fmaf(acc[mt][nt][h * 2], fv.x, sum);
                        sum = fmaf(acc[mt][nt][h * 2 + 1], fv.y, sum);
                    }
                    sum += __shfl_xor_sync(0xffffffffu, sum, 1);
                    sum += __shfl_xor_sync(0xffffffffu, sum, 2);
                    if ((lane & 3) == 0) {
                        int b = btile * 256 + p * 64 + fl;
                        g_partial[(size_t)(jt * 2 + nw) * 131072 + (size_t)b * 64 + c] = sum;
                    }
                }
            }
        }
    }
}

// ---------------- MLP: sum 8 slices + bias + relu + 64->32->1 ----------------
// 64 blocks x 32 threads: one warp per block, one b per thread.
__global__ void mlp_kernel(const float* __restrict__ b_proj, const float* __restrict__ W1,
                           const float* __restrict__ b1, const float* __restrict__ W2,
                           const float* __restrict__ b2, float* __restrict__ out) {
    __shared__ float sW1[2048], sb1[32], sW2[32], sbp[64];
    int tid = threadIdx.x;
    for (int i = tid; i < 2048; i += 32) sW1[i] = W1[i];
    if (tid < 32) { sb1[tid] = b1[tid]; sW2[tid] = W2[tid]; }
    for (int i = tid; i < 64; i += 32) sbp[i] = b_proj[i];
    __syncthreads();

    int b = blockIdx.x * 32 + tid;
    float h[64];
#pragma unroll
    for (int cg = 0; cg < 16; cg++) {
        float4 v = *(const float4*)&g_partial[(size_t)b * 64 + cg * 4];
#pragma unroll
        for (int s = 1; s < 8; s++) {
            float4 p = *(const float4*)&g_partial[(size_t)s * 131072 + (size_t)b * 64 + cg * 4];
            v.x += p.x; v.y += p.y; v.z += p.z; v.w += p.w;
        }
        h[cg * 4 + 0] = fmaxf(v.x + sbp[cg * 4 + 0], 0.f);
        h[cg * 4 + 1] = fmaxf(v.y + sbp[cg * 4 + 1], 0.f);
        h[cg * 4 + 2] = fmaxf(v.z + sbp[cg * 4 + 2], 0.f);
        h[cg * 4 + 3] = fmaxf(v.w + sbp[cg * 4 + 3], 0.f);
    }
    float logit = b2[0];
#pragma unroll
    for (int k = 0; k < 32; k++) {
        float a = sb1[k];
#pragma unroll
        for (int cc = 0; cc < 64; cc++)
            a = fmaf(h[cc], sW1[k * 64 + cc], a);
        logit = fmaf(fmaxf(a, 0.f), sW2[k], logit);
    }
    out[b] = logit;
}

// ---------------- launcher ----------------
extern "C" void kernel_launch(void* const* d_in, const int* in_sizes, int n_in,
                              void* d_out, int out_size) {
    const float* t_feat = (const float*)d_in[0];
    const float* f_feat = (const float*)d_in[1];
    const float* W_proj = (const float*)d_in[2];
    const float* b_proj = (const float*)d_in[3];
    const float* W1     = (const float*)d_in[4];
    const float* b1     = (const float*)d_in[5];
    const float* W2     = (const float*)d_in[6];
    const float* b2     = (const float*)d_in[7];
    float* out = (float*)d_out;

    cudaFuncSetAttribute(gemm_kernel, cudaFuncAttributeMaxDynamicSharedMemorySize, SMEM_GEMM);

    conv_kernel<<<33792, 256>>>(t_feat, W_proj);
    dim3 grid(8, 4, 64);   // (btile, jt, c) — btile fastest keeps W slice hot in L2
    gemm_kernel<<<grid, 256, SMEM_GEMM>>>(f_feat);
    mlp_kernel<<<64, 32>>>(b_proj, W1, b1, W2, b2, out);
}